// round 5
// baseline (speedup 1.0000x reference)
#include <cuda_runtime.h>
#include <cuda_bf16.h>
#include <cstdint>
#include <climits>

// Problem constants
#define NB 8
#define NL 2048
#define ND 128
#define EPSN 1e-8f
#define MARGIN_INT 500    // ~0.031 in sim units (127^2 = 16129), ~10 sigma
#define CCAP 64

// ---------------- scratch (no allocation allowed) ----------------
// __align__ is load-bearing: cp.async/ldg.128/uint32 stores require it and
// uint8_t device arrays otherwise get 1-byte ELF alignment.
__device__ __align__(128) float g_cn[NB * NL * ND];      // normalized ctx (fp32)
__device__ __align__(128) float g_en[NB * NL * ND];      // normalized ent (fp32)
__device__ __align__(128) uint8_t g_cni8[NB * NL * ND];  // int8 quantized cn
__device__ __align__(128) uint8_t g_eni8[NB * NL * ND];  // int8 quantized en
__device__ __align__(128) int g_idx[NB * NL];

// ---------------- PTX helpers (compute_103-safe) ----------------
__device__ __forceinline__ uint32_t smem_u32(const void* p) {
    uint32_t a;
    asm("{ .reg .u64 t; cvta.to.shared.u64 t, %1; cvt.u32.u64 %0, t; }"
        : "=r"(a) : "l"(p));
    return a;
}
__device__ __forceinline__ void ldm4(uint32_t* a, uint32_t addr) {
    asm volatile("ldmatrix.sync.aligned.m8n8.x4.shared.b16 {%0,%1,%2,%3}, [%4];"
                 : "=r"(a[0]), "=r"(a[1]), "=r"(a[2]), "=r"(a[3]) : "r"(addr));
}
__device__ __forceinline__ void mma_s8(int* c, const uint32_t* a, uint32_t b0,
                                       uint32_t b1) {
    asm volatile(
        "mma.sync.aligned.m16n8k32.row.col.s32.s8.s8.s32 "
        "{%0,%1,%2,%3}, {%4,%5,%6,%7}, {%8,%9}, {%0,%1,%2,%3};"
        : "+r"(c[0]), "+r"(c[1]), "+r"(c[2]), "+r"(c[3])
        : "r"(a[0]), "r"(a[1]), "r"(a[2]), "r"(a[3]), "r"(b0), "r"(b1));
}
#define CP_ASYNC16(dst, src) \
    asm volatile("cp.async.cg.shared.global [%0], [%1], 16;" :: "r"(dst), "l"(src))
#define CP_COMMIT() asm volatile("cp.async.commit_group;")
#define CP_WAIT(n)  asm volatile("cp.async.wait_group %0;" :: "n"(n))

// =================================================================
// Stage 1: L2-normalize; emit fp32 rows + int8 rows (q = rn(127*x)).
// =================================================================
__global__ void norm_kernel(const float* __restrict__ ctx) {
    int gwarp = (blockIdx.x * blockDim.x + threadIdx.x) >> 5;
    int lane  = threadIdx.x & 31;
    if (gwarp >= 2 * NB * NL) return;
    int which = gwarp >> 14;
    int r     = gwarp & (NB * NL - 1);
    int b = r >> 11, l = r & (NL - 1);
    const float4* src =
        (const float4*)(ctx + ((size_t)(b * 2 + which) * NL + l) * ND);
    float4 v = src[lane];
    float s = v.x * v.x + v.y * v.y + v.z * v.z + v.w * v.w;
#pragma unroll
    for (int o = 16; o; o >>= 1) s += __shfl_xor_sync(0xffffffffu, s, o);
    float inv = 1.0f / fmaxf(sqrtf(s), EPSN);
    float4 o4 = make_float4(v.x * inv, v.y * inv, v.z * inv, v.w * inv);
    float* dst = which ? g_en : g_cn;
    ((float4*)(dst + (size_t)r * ND))[lane] = o4;

    int q0 = __float2int_rn(o4.x * 127.0f);
    int q1 = __float2int_rn(o4.y * 127.0f);
    int q2 = __float2int_rn(o4.z * 127.0f);
    int q3 = __float2int_rn(o4.w * 127.0f);
    uint32_t p = (q0 & 0xff) | ((q1 & 0xff) << 8) | ((q2 & 0xff) << 16)
               | ((uint32_t)(q3 & 0xff) << 24);
    uint8_t* bdst = which ? g_eni8 : g_cni8;
    ((uint32_t*)(bdst + (size_t)r * ND))[lane] = p;
}

// =================================================================
// Stage 2: int8 IMMA sim-GEMM + fused argmax with candidate rescore.
// CTA: 128 l-rows, 256 threads (8 warps, 4x2 grid, 32x64 warp tiles).
// smem rows: 128 B int8 payload, stride 144 B (conflict-free ldmatrix).
// =================================================================
#define LDS8 144
#define SM_AT   0                         // 128*144 = 18432
#define SM_BT0  18432
#define SM_BT1  36864
#define SM_CS   55296                     // int32 cand sims 128*64*4 = 32768
#define SM_CI   88064                     // int32 cand idx          32768
#define SM_CNT  120832                    // int32 per-row count       512
#define SM_HM   121344                    // int32 half maxima [128][2] 1024
#define SM_SIM_TOTAL 122368

__global__ __launch_bounds__(256, 1) void simarg_kernel() {
    extern __shared__ char smc[];
    int* candS = (int*)(smc + SM_CS);
    int* candI = (int*)(smc + SM_CI);
    int* cnt   = (int*)(smc + SM_CNT);
    int* hmax  = (int*)(smc + SM_HM);

    int tid = threadIdx.x, w = tid >> 5, lane = tid & 31;
    int wy = w >> 1, wx = w & 1;
    int g = lane >> 2, t = lane & 3;
    int b = blockIdx.y, l0 = blockIdx.x * 128;

    if (tid < 128) cnt[tid] = 0;

    // load A tile (plain vectorized copy, 1024 x 16B)
    const uint4* asrc = (const uint4*)(g_cni8 + ((size_t)b * NL + l0) * ND);
#pragma unroll
    for (int i = tid; i < 1024; i += 256) {
        int row = i >> 3, c = i & 7;
        *(uint4*)(smc + SM_AT + row * LDS8 + c * 16) = asrc[row * 8 + c];
    }

    const char* esrc = (const char*)(g_eni8 + (size_t)b * NL * ND);
    uint32_t sb = smem_u32(smc);

    // prefetch B tile 0
#pragma unroll
    for (int i = tid; i < 1024; i += 256) {
        int row = i >> 3, c = i & 7;
        CP_ASYNC16(sb + SM_BT0 + row * LDS8 + c * 16,
                   esrc + (size_t)row * ND + c * 16);
    }
    CP_COMMIT();

    uint32_t arow = 32 * wy + (lane & 15);
    uint32_t abyte = (lane >> 4) * 16;
    uint32_t aaddr = sb + SM_AT + arow * LDS8 + abyte;
    uint32_t boff  = (64 * wx + (lane & 15)) * LDS8 + abyte;

    int rmax[2][2] = {{INT_MIN, INT_MIN}, {INT_MIN, INT_MIN}};

    for (int mt = 0; mt < 16; ++mt) {
        int cur = mt & 1;
        if (mt + 1 < 16) {
            int nb_ = SM_BT0 + ((mt + 1) & 1) * 18432;
#pragma unroll
            for (int i = tid; i < 1024; i += 256) {
                int row = i >> 3, c = i & 7;
                CP_ASYNC16(sb + nb_ + row * LDS8 + c * 16,
                           esrc + ((size_t)(mt + 1) * 128 + row) * ND + c * 16);
            }
            CP_COMMIT();
            CP_WAIT(1);
        } else {
            CP_WAIT(0);
        }
        __syncthreads();

        uint32_t bbase = sb + SM_BT0 + cur * 18432 + boff;

        int acc[2][4][2][4];  // [f][jb][sub][c]
#pragma unroll
        for (int f = 0; f < 2; ++f)
#pragma unroll
            for (int jb = 0; jb < 4; ++jb)
#pragma unroll
                for (int s2 = 0; s2 < 2; ++s2)
#pragma unroll
                    for (int c = 0; c < 4; ++c) acc[f][jb][s2][c] = 0;

#pragma unroll
        for (int kc = 0; kc < 4; ++kc) {
            uint32_t a0[4], a1[4];
            ldm4(a0, aaddr + kc * 32);
            ldm4(a1, aaddr + 16 * LDS8 + kc * 32);
#pragma unroll
            for (int jb = 0; jb < 4; ++jb) {
                uint32_t bb[4];
                ldm4(bb, bbase + jb * 16 * LDS8 + kc * 32);
                mma_s8(acc[0][jb][0], a0, bb[0], bb[2]);
                mma_s8(acc[0][jb][1], a0, bb[1], bb[3]);
                mma_s8(acc[1][jb][0], a1, bb[0], bb[2]);
                mma_s8(acc[1][jb][1], a1, bb[1], bb[3]);
            }
        }

        // epilogue: running int max + candidate append
#pragma unroll
        for (int f = 0; f < 2; ++f)
#pragma unroll
            for (int h = 0; h < 2; ++h) {
                int tm = INT_MIN;
#pragma unroll
                for (int jb = 0; jb < 4; ++jb)
#pragma unroll
                    for (int s2 = 0; s2 < 2; ++s2)
                        tm = max(tm, max(acc[f][jb][s2][2 * h],
                                         acc[f][jb][s2][2 * h + 1]));
                tm = max(tm, __shfl_xor_sync(0xffffffffu, tm, 1));
                tm = max(tm, __shfl_xor_sync(0xffffffffu, tm, 2));
                int nm = max(rmax[f][h], tm);
                rmax[f][h] = nm;
                int thr = nm - MARGIN_INT;
                int r = 32 * wy + 16 * f + 8 * h + g;
#pragma unroll
                for (int jb = 0; jb < 4; ++jb)
#pragma unroll
                    for (int s2 = 0; s2 < 2; ++s2)
#pragma unroll
                        for (int c = 0; c < 2; ++c) {
                            int v = acc[f][jb][s2][2 * h + c];
                            if (v >= thr) {
                                int pos = atomicAdd(&cnt[r], 1);
                                if (pos < CCAP) {
                                    candS[r * CCAP + pos] = v;
                                    candI[r * CCAP + pos] =
                                        mt * 128 + wx * 64 + jb * 16 + s2 * 8 +
                                        2 * t + c;
                                }
                            }
                        }
            }
        __syncthreads();  // Bt[cur] fully consumed before refill
    }

    // publish per-warp-half row maxima
    if (t == 0) {
#pragma unroll
        for (int f = 0; f < 2; ++f)
#pragma unroll
            for (int h = 0; h < 2; ++h)
                hmax[(32 * wy + 16 * f + 8 * h + g) * 2 + wx] = rmax[f][h];
    }
    __syncthreads();

    // filter + exact fp32 rescore: 2 threads per row
    {
        int r = tid >> 1;
        int Mb = max(hmax[r * 2], hmax[r * 2 + 1]);
        int thr = Mb - MARGIN_INT;
        int n = min(cnt[r], CCAP);
        float bv = -1e30f;
        int bi = 0x7fffffff;
        const float4* xa = (const float4*)(g_cn + ((size_t)b * NL + l0 + r) * ND);
        for (int e = (tid & 1); e < n; e += 2) {
            if (candS[r * CCAP + e] < thr) continue;
            int m = candI[r * CCAP + e];
            const float4* xb = (const float4*)(g_en + ((size_t)b * NL + m) * ND);
            float s0 = 0, s1 = 0, s2 = 0, s3 = 0;
#pragma unroll
            for (int q = 0; q < 32; ++q) {
                float4 A = xa[q];
                float4 Bv = xb[q];
                s0 += A.x * Bv.x; s1 += A.y * Bv.y;
                s2 += A.z * Bv.z; s3 += A.w * Bv.w;
            }
            float s = (s0 + s1) + (s2 + s3);
            if (s > bv || (s == bv && m < bi)) { bv = s; bi = m; }
        }
        __syncthreads();
        float* fS = (float*)candS;
        fS[tid] = bv;
        candI[tid] = bi;
        __syncthreads();
        if (tid < 128) {
            float v0 = fS[tid * 2], v1 = fS[tid * 2 + 1];
            int i0 = candI[tid * 2], i1 = candI[tid * 2 + 1];
            int best = (v1 > v0 || (v1 == v0 && i1 < i0)) ? i1 : i0;
            g_idx[b * NL + l0 + tid] = best;
        }
    }
}

// =================================================================
// Stage 3: per-token 2-row MLP + reduction (unchanged).
// =================================================================
#define W1S 132

__global__ __launch_bounds__(128) void mlp_kernel(
    const float* __restrict__ W1, const float* __restrict__ b1,
    const float* __restrict__ W2, const float* __restrict__ b2,
    float* __restrict__ out) {
    extern __shared__ float sm[];
    float* W1t  = sm;
    float* rows = sm + 128 * W1S;
    float* part = sm + 128 * W1S + 16 * 128;

    int tid  = threadIdx.x;
    int lane = tid & 31;
    int wp   = tid >> 5;

#pragma unroll
    for (int i = 0; i < 128; ++i) {
        int flat = i * 128 + tid;
        int j = flat & 127, k = flat >> 7;
        W1t[j * W1S + k] = W1[k * 128 + j];
    }
    float bias = b1[tid];
    float w2   = W2[tid];
    float bb2  = b2[0];

    int tok0 = blockIdx.x * 64;
    for (int g0 = 0; g0 < 64; g0 += 8) {
        __syncthreads();
#pragma unroll
        for (int i = 0; i < 16; ++i) {
            int flat = i * 128 + tid;
            int r = flat >> 7, k = flat & 127;
            int tok = tok0 + g0 + (r >> 1);
            const float* src;
            if (r & 1) {
                int bb = tok >> 11;
                int mi = g_idx[tok];
                src = g_en + ((size_t)(bb << 11) + mi) * ND;
            } else {
                src = g_cn + (size_t)tok * ND;
            }
            rows[r * 128 + k] = src[k];
        }
        __syncthreads();

        float acc[16];
#pragma unroll
        for (int r = 0; r < 16; ++r) acc[r] = bias;

#pragma unroll 4
        for (int kq = 0; kq < 32; ++kq) {
            float4 w4 = *(const float4*)(W1t + tid * W1S + kq * 4);
#pragma unroll
            for (int r = 0; r < 16; ++r) {
                float4 x = *(const float4*)(rows + r * 128 + kq * 4);
                acc[r] += w4.x * x.x + w4.y * x.y + w4.z * x.z + w4.w * x.w;
            }
        }

        float c[8];
#pragma unroll
        for (int g = 0; g < 8; ++g) {
            float h0 = fmaxf(acc[2 * g], 0.0f);
            float h1 = fmaxf(acc[2 * g + 1], 0.0f);
            c[g] = (h0 + h1) * w2;
        }
#pragma unroll
        for (int g = 0; g < 8; ++g) {
            float v = c[g];
#pragma unroll
            for (int o = 16; o; o >>= 1) v += __shfl_xor_sync(0xffffffffu, v, o);
            c[g] = v;
        }
        if (lane == 0) {
#pragma unroll
            for (int g = 0; g < 8; ++g) part[g * 4 + wp] = c[g];
        }
        __syncthreads();
        if (tid < 8) {
            float s = part[tid * 4] + part[tid * 4 + 1] +
                      part[tid * 4 + 2] + part[tid * 4 + 3];
            out[tok0 + g0 + tid] = s + 2.0f * bb2;
        }
    }
}

// =================================================================
// launch
// =================================================================
extern "C" void kernel_launch(void* const* d_in, const int* in_sizes, int n_in,
                              void* d_out, int out_size) {
    const float* context = (const float*)d_in[0];
    const float* W1      = (const float*)d_in[1];
    const float* b1      = (const float*)d_in[2];
    const float* W2      = (const float*)d_in[3];
    const float* b2      = (const float*)d_in[4];
    float* out           = (float*)d_out;

    {
        int warps = 2 * NB * NL;
        int threads = 256;
        int blocks = (warps * 32 + threads - 1) / threads;
        norm_kernel<<<blocks, threads>>>(context);
    }
    {
        cudaFuncSetAttribute(simarg_kernel,
                             cudaFuncAttributeMaxDynamicSharedMemorySize,
                             SM_SIM_TOTAL);
        dim3 grid(NL / 128, NB);
        simarg_kernel<<<grid, 256, SM_SIM_TOTAL>>>();
    }
    {
        size_t smem = (size_t)(128 * W1S + 16 * 128 + 64) * sizeof(float);
        cudaFuncSetAttribute(mlp_kernel,
                             cudaFuncAttributeMaxDynamicSharedMemorySize,
                             (int)smem);
        mlp_kernel<<<NB * NL / 64, 128, smem>>>(W1, b1, W2, b2, out);
    }
}

// round 6
// speedup vs baseline: 1.1803x; 1.1803x over previous
#include <cuda_runtime.h>
#include <cuda_bf16.h>
#include <cstdint>

// Problem constants
#define NB 8
#define NL 2048
#define ND 128
#define EPSN 1e-8f
#define MARGIN 0.02f
#define CCAP 48

// ---------------- scratch (no allocation allowed) ----------------
__device__ __align__(128) float g_cn[NB * NL * ND];            // normalized ctx
__device__ __align__(128) float g_en[NB * NL * ND];            // normalized ent
__device__ __align__(128) __nv_bfloat16 g_cnbf[NB * NL * ND];  // bf16(cn)
__device__ __align__(128) __nv_bfloat16 g_enbf[NB * NL * ND];  // bf16(en)
__device__ __align__(128) float g_scn[NB * NL];                // s(cn row)
__device__ __align__(128) float g_sen[NB * NL];                // s(en row)

// ---------------- PTX helpers (compute_103-safe) ----------------
__device__ __forceinline__ uint32_t smem_u32(const void* p) {
    uint32_t a;
    asm("{ .reg .u64 t; cvta.to.shared.u64 t, %1; cvt.u32.u64 %0, t; }"
        : "=r"(a) : "l"(p));
    return a;
}
__device__ __forceinline__ void ldmA(uint32_t* a, uint32_t addr) {
    asm volatile("ldmatrix.sync.aligned.m8n8.x4.shared.b16 {%0,%1,%2,%3}, [%4];"
                 : "=r"(a[0]), "=r"(a[1]), "=r"(a[2]), "=r"(a[3]) : "r"(addr));
}
__device__ __forceinline__ void ldmB(uint32_t* b, uint32_t addr) {
    asm volatile("ldmatrix.sync.aligned.m8n8.x2.shared.b16 {%0,%1}, [%2];"
                 : "=r"(b[0]), "=r"(b[1]) : "r"(addr));
}
__device__ __forceinline__ void mma16816(float* c, const uint32_t* a,
                                         const uint32_t* b) {
    asm volatile(
        "mma.sync.aligned.m16n8k16.row.col.f32.bf16.bf16.f32 "
        "{%0,%1,%2,%3}, {%4,%5,%6,%7}, {%8,%9}, {%0,%1,%2,%3};"
        : "+f"(c[0]), "+f"(c[1]), "+f"(c[2]), "+f"(c[3])
        : "r"(a[0]), "r"(a[1]), "r"(a[2]), "r"(a[3]), "r"(b[0]), "r"(b[1]));
}
#define CP_ASYNC16(dst, src) \
    asm volatile("cp.async.cg.shared.global [%0], [%1], 16;" :: "r"(dst), "l"(src))
#define CP_COMMIT() asm volatile("cp.async.commit_group;")
#define CP_WAIT(n)  asm volatile("cp.async.wait_group %0;" :: "n"(n))

// =================================================================
// Stage 1: fused L2-normalize + per-row MLP scalar.
//   s(row) = relu(row.W1 + b1) @ W2   (b2 added in stage 2)
// Block: 128 threads (thread j = neuron j), 64 rows per block in
// chunks of 8. Emits g_cn/g_en fp32, bf16 copies, and g_scn/g_sen.
// Norm math is bit-identical to prior rounds (same lane grouping).
// =================================================================
#define W1S 132
#define NM_W1   0                       // 128*132 floats = 67584 B
#define NM_ROWS 67584                   // 8*128 floats   = 4096 B
#define NM_INV  71680                   // 8 floats
#define NM_PART 71712                   // 8*4 floats
#define NM_TOTAL 71872

__global__ __launch_bounds__(128) void normmlp_kernel(
    const float* __restrict__ ctx, const float* __restrict__ W1,
    const float* __restrict__ b1, const float* __restrict__ W2) {
    extern __shared__ float sm[];
    float* W1t  = sm + NM_W1 / 4;
    float* rows = sm + NM_ROWS / 4;
    float* invs = sm + NM_INV / 4;
    float* part = sm + NM_PART / 4;

    int tid = threadIdx.x, lane = tid & 31, wp = tid >> 5;

    // load W1 transposed: W1t[j][k] = W1[k][j]
#pragma unroll
    for (int i = 0; i < 128; ++i) {
        int flat = i * 128 + tid;
        int j = flat & 127, k = flat >> 7;
        W1t[j * W1S + k] = W1[k * 128 + j];
    }
    float bias = b1[tid];
    float w2   = W2[tid];

    int r0 = blockIdx.x * 64;
    for (int g0 = 0; g0 < 64; g0 += 8) {
        __syncthreads();  // rows/part reuse guard
        // load 8 raw rows (coalesced)
#pragma unroll
        for (int r = 0; r < 8; ++r) {
            int vr = r0 + g0 + r;
            int which = vr >> 14, rr = vr & 16383;
            int b = rr >> 11, l = rr & 2047;
            rows[r * 128 + tid] =
                ctx[((size_t)(b * 2 + which) * NL + l) * ND + tid];
        }
        __syncthreads();
        // norms: warp wp handles rows wp and wp+4 (same lane-grouping as
        // the original norm kernel -> bitwise-identical inv)
#pragma unroll
        for (int rep = 0; rep < 2; ++rep) {
            int r = wp + rep * 4;
            float4 v = ((const float4*)(rows + r * 128))[lane];
            float s = v.x * v.x + v.y * v.y + v.z * v.z + v.w * v.w;
#pragma unroll
            for (int o = 16; o; o >>= 1) s += __shfl_xor_sync(0xffffffffu, s, o);
            if (lane == 0) invs[r] = 1.0f / fmaxf(sqrtf(s), EPSN);
        }
        __syncthreads();
        // scale + emit fp32 and bf16
#pragma unroll
        for (int r = 0; r < 8; ++r) {
            int vr = r0 + g0 + r;
            int which = vr >> 14, rr = vr & 16383;
            float v = rows[r * 128 + tid] * invs[r];
            rows[r * 128 + tid] = v;
            (which ? g_en : g_cn)[(size_t)rr * ND + tid] = v;
            (which ? g_enbf : g_cnbf)[(size_t)rr * ND + tid] =
                __float2bfloat16(v);
        }
        __syncthreads();
        // MLP: thread = neuron j, 8 rows at once
        float acc[8];
#pragma unroll
        for (int r = 0; r < 8; ++r) acc[r] = bias;
#pragma unroll 4
        for (int kq = 0; kq < 32; ++kq) {
            float4 w4 = *(const float4*)(W1t + tid * W1S + kq * 4);
#pragma unroll
            for (int r = 0; r < 8; ++r) {
                float4 x = *(const float4*)(rows + r * 128 + kq * 4);
                acc[r] += w4.x * x.x + w4.y * x.y + w4.z * x.z + w4.w * x.w;
            }
        }
#pragma unroll
        for (int r = 0; r < 8; ++r) {
            float c = fmaxf(acc[r], 0.0f) * w2;
#pragma unroll
            for (int o = 16; o; o >>= 1) c += __shfl_xor_sync(0xffffffffu, c, o);
            if (lane == 0) part[r * 4 + wp] = c;
        }
        __syncthreads();
        if (tid < 8) {
            float s = part[tid * 4] + part[tid * 4 + 1] +
                      part[tid * 4 + 2] + part[tid * 4 + 3];
            int vr = r0 + g0 + tid;
            int which = vr >> 14, rr = vr & 16383;
            (which ? g_sen : g_scn)[rr] = s;
        }
    }
}

// =================================================================
// Stage 2: HMMA bf16 sim-GEMM + fused argmax (R3-proven math) with
// 3-stage cp.async pipeline; writes final output directly.
// CTA: 128 l-rows, 256 threads (8 warps, 4x2 grid, 32x64 tiles).
// =================================================================
#define LDB 272
#define SM_AT   0                           // 34816
#define SM_BT0  34816                       // 3 buffers x 34816
#define SM_CS   139264                      // 128*48*4 = 24576
#define SM_CI   163840                      // 24576
#define SM_CNT  188416                      // 512
#define SM_HM   188928                      // 1024
#define SM_SIM_TOTAL 189952

__global__ __launch_bounds__(256, 1) void simarg_kernel(
    const float* __restrict__ b2, float* __restrict__ out) {
    extern __shared__ char smc[];
    float* candV = (float*)(smc + SM_CS);
    int*   candI = (int*)(smc + SM_CI);
    int*   cnt   = (int*)(smc + SM_CNT);
    float* hmax  = (float*)(smc + SM_HM);

    int tid = threadIdx.x, w = tid >> 5, lane = tid & 31;
    int wy = w >> 1, wx = w & 1;
    int g = lane >> 2, t = lane & 3;
    int b = blockIdx.y, l0 = blockIdx.x * 128;

    if (tid < 128) cnt[tid] = 0;

    // load A tile (plain vectorized copy)
    const uint4* asrc = (const uint4*)(g_cnbf + ((size_t)b * NL + l0) * ND);
#pragma unroll
    for (int i = tid; i < 2048; i += 256) {
        int row = i >> 4, c = i & 15;
        *(uint4*)(smc + SM_AT + row * LDB + c * 16) = asrc[row * 16 + c];
    }

    const char* esrc = (const char*)(g_enbf + (size_t)b * NL * ND);
    uint32_t sb = smem_u32(smc);

    // prefetch B tiles 0 and 1
#pragma unroll
    for (int q = 0; q < 2; ++q) {
#pragma unroll
        for (int i = tid; i < 2048; i += 256) {
            int row = i >> 4, c = i & 15;
            CP_ASYNC16(sb + SM_BT0 + q * 34816 + row * LDB + c * 16,
                       esrc + ((size_t)q * 128 + row) * 256 + c * 16);
        }
        CP_COMMIT();
    }

    uint32_t aaddr = sb + SM_AT + ((32 * wy + (lane & 15)) * LDB + (lane >> 4) * 16);
    uint32_t baddr0 = ((lane & 7)) * LDB + ((lane >> 3) & 1) * 16;

    float rmax[2][2] = {{-2.0f, -2.0f}, {-2.0f, -2.0f}};

    for (int mt = 0; mt < 16; ++mt) {
        if (mt < 15) { CP_WAIT(1); } else { CP_WAIT(0); }
        __syncthreads();

        uint32_t bbase = sb + SM_BT0 + (mt % 3) * 34816 + baddr0 + wx * 64 * LDB;

        float acc[2][8][4];
#pragma unroll
        for (int f = 0; f < 2; ++f)
#pragma unroll
            for (int j = 0; j < 8; ++j)
#pragma unroll
                for (int c = 0; c < 4; ++c) acc[f][j][c] = 0.0f;

#pragma unroll
        for (int kc = 0; kc < 8; ++kc) {
            uint32_t a0[4], a1[4];
            ldmA(a0, aaddr + kc * 32);
            ldmA(a1, aaddr + 16 * LDB + kc * 32);
#pragma unroll
            for (int j = 0; j < 8; ++j) {
                uint32_t bb[2];
                ldmB(bb, bbase + j * 8 * LDB + kc * 32);
                mma16816(acc[0][j], a0, bb);
                mma16816(acc[1][j], a1, bb);
            }
        }

        // epilogue: running max + candidate append (R3-proven)
#pragma unroll
        for (int f = 0; f < 2; ++f)
#pragma unroll
            for (int h = 0; h < 2; ++h) {
                float tm = -2.0f;
#pragma unroll
                for (int j = 0; j < 8; ++j)
                    tm = fmaxf(tm, fmaxf(acc[f][j][2 * h], acc[f][j][2 * h + 1]));
                tm = fmaxf(tm, __shfl_xor_sync(0xffffffffu, tm, 1));
                tm = fmaxf(tm, __shfl_xor_sync(0xffffffffu, tm, 2));
                float nm = fmaxf(rmax[f][h], tm);
                rmax[f][h] = nm;
                float thr = nm - MARGIN;
                int r = 32 * wy + 16 * f + 8 * h + g;
#pragma unroll
                for (int j = 0; j < 8; ++j)
#pragma unroll
                    for (int c = 0; c < 2; ++c) {
                        float v = acc[f][j][2 * h + c];
                        if (v >= thr) {
                            int pos = atomicAdd(&cnt[r], 1);
                            if (pos < CCAP) {
                                candV[r * CCAP + pos] = v;
                                candI[r * CCAP + pos] =
                                    mt * 128 + wx * 64 + j * 8 + 2 * t + c;
                            }
                        }
                    }
            }
        __syncthreads();  // all reads of buf (mt%3) done

        if (mt + 2 < 16) {  // prefetch tile mt+2 into buf (mt+2)%3
            int nb_ = SM_BT0 + ((mt + 2) % 3) * 34816;
#pragma unroll
            for (int i = tid; i < 2048; i += 256) {
                int row = i >> 4, c = i & 15;
                CP_ASYNC16(sb + nb_ + row * LDB + c * 16,
                           esrc + ((size_t)(mt + 2) * 128 + row) * 256 + c * 16);
            }
            CP_COMMIT();
        }
    }

    // publish per-warp-half row maxima
    if (t == 0) {
#pragma unroll
        for (int f = 0; f < 2; ++f)
#pragma unroll
            for (int h = 0; h < 2; ++h)
                hmax[(32 * wy + 16 * f + 8 * h + g) * 2 + wx] = rmax[f][h];
    }
    __syncthreads();

    // filter + exact fp32 rescore: 2 threads per row; then write output
    {
        int r = tid >> 1;
        float Mb = fmaxf(hmax[r * 2], hmax[r * 2 + 1]);
        float thr = Mb - MARGIN;
        int n = min(cnt[r], CCAP);
        float bv = -1e30f;
        int bi = 0x7fffffff;
        const float4* xa = (const float4*)(g_cn + ((size_t)b * NL + l0 + r) * ND);
        for (int e = (tid & 1); e < n; e += 2) {
            if (candV[r * CCAP + e] < thr) continue;
            int m = candI[r * CCAP + e];
            const float4* xb = (const float4*)(g_en + ((size_t)b * NL + m) * ND);
            float s0 = 0, s1 = 0, s2 = 0, s3 = 0;
#pragma unroll
            for (int q = 0; q < 32; ++q) {
                float4 A = xa[q];
                float4 Bv = xb[q];
                s0 += A.x * Bv.x; s1 += A.y * Bv.y;
                s2 += A.z * Bv.z; s3 += A.w * Bv.w;
            }
            float s = (s0 + s1) + (s2 + s3);
            if (s > bv || (s == bv && m < bi)) { bv = s; bi = m; }
        }
        __syncthreads();
        candV[tid] = bv;
        candI[tid] = bi;
        __syncthreads();
        if (tid < 128) {
            float v0 = candV[tid * 2], v1 = candV[tid * 2 + 1];
            int i0 = candI[tid * 2], i1 = candI[tid * 2 + 1];
            int best = (v1 > v0 || (v1 == v0 && i1 < i0)) ? i1 : i0;
            float bb2 = b2[0];
            out[b * NL + l0 + tid] = g_scn[b * NL + l0 + tid] +
                                     g_sen[b * NL + best] + 2.0f * bb2;
        }
    }
}

// =================================================================
// launch
// =================================================================
extern "C" void kernel_launch(void* const* d_in, const int* in_sizes, int n_in,
                              void* d_out, int out_size) {
    const float* context = (const float*)d_in[0];
    const float* W1      = (const float*)d_in[1];
    const float* b1      = (const float*)d_in[2];
    const float* W2      = (const float*)d_in[3];
    const float* b2      = (const float*)d_in[4];
    float* out           = (float*)d_out;

    {
        cudaFuncSetAttribute(normmlp_kernel,
                             cudaFuncAttributeMaxDynamicSharedMemorySize,
                             NM_TOTAL);
        normmlp_kernel<<<512, 128, NM_TOTAL>>>(context, W1, b1, W2);
    }
    {
        cudaFuncSetAttribute(simarg_kernel,
                             cudaFuncAttributeMaxDynamicSharedMemorySize,
                             SM_SIM_TOTAL);
        dim3 grid(NL / 128, NB);
        simarg_kernel<<<grid, 256, SM_SIM_TOTAL>>>(b2, out);
    }
}

// round 8
// speedup vs baseline: 1.2475x; 1.0570x over previous
#include <cuda_runtime.h>
#include <cuda_bf16.h>
#include <cstdint>

// Problem constants
#define NB 8
#define NL 2048
#define ND 128
#define EPSN 1e-8f
#define MARGIN 0.02f
#define CCAP 48

// ---------------- scratch (no allocation allowed) ----------------
__device__ __align__(128) float g_cn[NB * NL * ND];            // normalized ctx
__device__ __align__(128) float g_en[NB * NL * ND];            // normalized ent
__device__ __align__(128) __nv_bfloat16 g_cnbf[NB * NL * ND];  // bf16(cn)
__device__ __align__(128) __nv_bfloat16 g_enbf[NB * NL * ND];  // bf16(en)
__device__ __align__(128) float g_scn[NB * NL];                // s(cn row)
__device__ __align__(128) float g_sen[NB * NL];                // s(en row)

// ---------------- PTX helpers (compute_103-safe) ----------------
__device__ __forceinline__ uint32_t smem_u32(const void* p) {
    uint32_t a;
    asm("{ .reg .u64 t; cvta.to.shared.u64 t, %1; cvt.u32.u64 %0, t; }"
        : "=r"(a) : "l"(p));
    return a;
}
__device__ __forceinline__ void ldmA(uint32_t* a, uint32_t addr) {
    asm volatile("ldmatrix.sync.aligned.m8n8.x4.shared.b16 {%0,%1,%2,%3}, [%4];"
                 : "=r"(a[0]), "=r"(a[1]), "=r"(a[2]), "=r"(a[3]) : "r"(addr));
}
__device__ __forceinline__ void ldmB(uint32_t* b, uint32_t addr) {
    asm volatile("ldmatrix.sync.aligned.m8n8.x2.shared.b16 {%0,%1}, [%2];"
                 : "=r"(b[0]), "=r"(b[1]) : "r"(addr));
}
__device__ __forceinline__ void mma16816(float* c, const uint32_t* a,
                                         const uint32_t* b) {
    asm volatile(
        "mma.sync.aligned.m16n8k16.row.col.f32.bf16.bf16.f32 "
        "{%0,%1,%2,%3}, {%4,%5,%6,%7}, {%8,%9}, {%0,%1,%2,%3};"
        : "+f"(c[0]), "+f"(c[1]), "+f"(c[2]), "+f"(c[3])
        : "r"(a[0]), "r"(a[1]), "r"(a[2]), "r"(a[3]), "r"(b[0]), "r"(b[1]));
}
#define CP_ASYNC16(dst, src) \
    asm volatile("cp.async.cg.shared.global [%0], [%1], 16;" :: "r"(dst), "l"(src))
#define CP_COMMIT() asm volatile("cp.async.commit_group;")
#define CP_WAIT(n)  asm volatile("cp.async.wait_group %0;" :: "n"(n))

// =================================================================
// Stage 1: L2-normalize; emit fp32 rows + bf16 rows (proven, 9.2us).
// =================================================================
__global__ void norm_kernel(const float* __restrict__ ctx) {
    int gwarp = (blockIdx.x * blockDim.x + threadIdx.x) >> 5;
    int lane  = threadIdx.x & 31;
    if (gwarp >= 2 * NB * NL) return;
    int which = gwarp >> 14;
    int r     = gwarp & (NB * NL - 1);
    int b = r >> 11, l = r & (NL - 1);
    const float4* src =
        (const float4*)(ctx + ((size_t)(b * 2 + which) * NL + l) * ND);
    float4 v = src[lane];
    float s = v.x * v.x + v.y * v.y + v.z * v.z + v.w * v.w;
#pragma unroll
    for (int o = 16; o; o >>= 1) s += __shfl_xor_sync(0xffffffffu, s, o);
    float inv = 1.0f / fmaxf(sqrtf(s), EPSN);
    float4 o4 = make_float4(v.x * inv, v.y * inv, v.z * inv, v.w * inv);
    float* dst = which ? g_en : g_cn;
    ((float4*)(dst + (size_t)r * ND))[lane] = o4;

    __nv_bfloat16* bdst = which ? g_enbf : g_cnbf;
    __nv_bfloat162* hp = (__nv_bfloat162*)(bdst + (size_t)r * ND + lane * 4);
    hp[0] = __halves2bfloat162(__float2bfloat16(o4.x), __float2bfloat16(o4.y));
    hp[1] = __halves2bfloat162(__float2bfloat16(o4.z), __float2bfloat16(o4.w));
}

// =================================================================
// Stage 2: per-row MLP scalar s(row) = relu(row.W1+b1)@W2 for all
// 32768 rows (cn then en). Structure = proven R3 mlp_kernel minus
// the gather (sequential row reads).
// =================================================================
#define W1S 132
#define SMLP_ROWS (128 * W1S)           // float offset of rows[]
#define SMLP_PART (SMLP_ROWS + 16 * 128)
#define SMLP_TOTAL ((SMLP_PART + 64) * 4)

__global__ __launch_bounds__(128) void smlp_kernel(
    const float* __restrict__ W1, const float* __restrict__ b1,
    const float* __restrict__ W2) {
    extern __shared__ float sm[];
    float* W1t  = sm;
    float* rows = sm + SMLP_ROWS;
    float* part = sm + SMLP_PART;

    int tid = threadIdx.x, lane = tid & 31, wp = tid >> 5;

#pragma unroll
    for (int i = 0; i < 128; ++i) {
        int flat = i * 128 + tid;
        int j = flat & 127, k = flat >> 7;
        W1t[j * W1S + k] = W1[k * 128 + j];
    }
    float bias = b1[tid];
    float w2   = W2[tid];

    int r0 = blockIdx.x * 64;
    for (int g0 = 0; g0 < 64; g0 += 16) {
        __syncthreads();
#pragma unroll
        for (int i = 0; i < 16; ++i) {
            int flat = i * 128 + tid;
            int r = flat >> 7, k = flat & 127;
            int vr = r0 + g0 + r;
            const float* src = (vr < NB * NL)
                ? g_cn + (size_t)vr * ND
                : g_en + (size_t)(vr - NB * NL) * ND;
            rows[r * 128 + k] = src[k];
        }
        __syncthreads();

        float acc[16];
#pragma unroll
        for (int r = 0; r < 16; ++r) acc[r] = bias;
#pragma unroll 4
        for (int kq = 0; kq < 32; ++kq) {
            float4 w4 = *(const float4*)(W1t + tid * W1S + kq * 4);
#pragma unroll
            for (int r = 0; r < 16; ++r) {
                float4 x = *(const float4*)(rows + r * 128 + kq * 4);
                acc[r] += w4.x * x.x + w4.y * x.y + w4.z * x.z + w4.w * x.w;
            }
        }
#pragma unroll
        for (int r = 0; r < 16; ++r) {
            float c = fmaxf(acc[r], 0.0f) * w2;
#pragma unroll
            for (int o = 16; o; o >>= 1) c += __shfl_xor_sync(0xffffffffu, c, o);
            if (lane == 0) part[r * 4 + wp] = c;
        }
        __syncthreads();
        if (tid < 16) {
            float s = part[tid * 4] + part[tid * 4 + 1] +
                      part[tid * 4 + 2] + part[tid * 4 + 3];
            int vr = r0 + g0 + tid;
            if (vr < NB * NL) g_scn[vr] = s;
            else              g_sen[vr - NB * NL] = s;
        }
    }
}

// =================================================================
// Stage 3: HMMA sim-GEMM + fused argmax — BYTE-IDENTICAL to the R6
// pass (76.7us measured): M=128, 3-stage cp.async pipeline, direct
// output via g_scn/g_sen.
// =================================================================
#define LDB 272
#define SM_AT   0                           // 34816
#define SM_BT0  34816                       // 3 buffers x 34816
#define SM_CS   139264                      // 128*48*4 = 24576
#define SM_CI   163840                      // 24576
#define SM_CNT  188416                      // 512
#define SM_HM   188928                      // 1024
#define SM_SIM_TOTAL 189952

__global__ __launch_bounds__(256, 1) void simarg_kernel(
    const float* __restrict__ b2, float* __restrict__ out) {
    extern __shared__ char smc[];
    float* candV = (float*)(smc + SM_CS);
    int*   candI = (int*)(smc + SM_CI);
    int*   cnt   = (int*)(smc + SM_CNT);
    float* hmax  = (float*)(smc + SM_HM);

    int tid = threadIdx.x, w = tid >> 5, lane = tid & 31;
    int wy = w >> 1, wx = w & 1;
    int g = lane >> 2, t = lane & 3;
    int b = blockIdx.y, l0 = blockIdx.x * 128;

    if (tid < 128) cnt[tid] = 0;

    // load A tile (plain vectorized copy)
    const uint4* asrc = (const uint4*)(g_cnbf + ((size_t)b * NL + l0) * ND);
#pragma unroll
    for (int i = tid; i < 2048; i += 256) {
        int row = i >> 4, c = i & 15;
        *(uint4*)(smc + SM_AT + row * LDB + c * 16) = asrc[row * 16 + c];
    }

    const char* esrc = (const char*)(g_enbf + (size_t)b * NL * ND);
    uint32_t sb = smem_u32(smc);

    // prefetch B tiles 0 and 1
#pragma unroll
    for (int q = 0; q < 2; ++q) {
#pragma unroll
        for (int i = tid; i < 2048; i += 256) {
            int row = i >> 4, c = i & 15;
            CP_ASYNC16(sb + SM_BT0 + q * 34816 + row * LDB + c * 16,
                       esrc + ((size_t)q * 128 + row) * 256 + c * 16);
        }
        CP_COMMIT();
    }

    uint32_t aaddr = sb + SM_AT + ((32 * wy + (lane & 15)) * LDB + (lane >> 4) * 16);
    uint32_t baddr0 = ((lane & 7)) * LDB + ((lane >> 3) & 1) * 16;

    float rmax[2][2] = {{-2.0f, -2.0f}, {-2.0f, -2.0f}};

    for (int mt = 0; mt < 16; ++mt) {
        if (mt < 15) { CP_WAIT(1); } else { CP_WAIT(0); }
        __syncthreads();

        uint32_t bbase = sb + SM_BT0 + (mt % 3) * 34816 + baddr0 + wx * 64 * LDB;

        float acc[2][8][4];
#pragma unroll
        for (int f = 0; f < 2; ++f)
#pragma unroll
            for (int j = 0; j < 8; ++j)
#pragma unroll
                for (int c = 0; c < 4; ++c) acc[f][j][c] = 0.0f;

#pragma unroll
        for (int kc = 0; kc < 8; ++kc) {
            uint32_t a0[4], a1[4];
            ldmA(a0, aaddr + kc * 32);
            ldmA(a1, aaddr + 16 * LDB + kc * 32);
#pragma unroll
            for (int j = 0; j < 8; ++j) {
                uint32_t bb[2];
                ldmB(bb, bbase + j * 8 * LDB + kc * 32);
                mma16816(acc[0][j], a0, bb);
                mma16816(acc[1][j], a1, bb);
            }
        }

        // epilogue: running max + candidate append (R3-proven)
#pragma unroll
        for (int f = 0; f < 2; ++f)
#pragma unroll
            for (int h = 0; h < 2; ++h) {
                float tm = -2.0f;
#pragma unroll
                for (int j = 0; j < 8; ++j)
                    tm = fmaxf(tm, fmaxf(acc[f][j][2 * h], acc[f][j][2 * h + 1]));
                tm = fmaxf(tm, __shfl_xor_sync(0xffffffffu, tm, 1));
                tm = fmaxf(tm, __shfl_xor_sync(0xffffffffu, tm, 2));
                float nm = fmaxf(rmax[f][h], tm);
                rmax[f][h] = nm;
                float thr = nm - MARGIN;
                int r = 32 * wy + 16 * f + 8 * h + g;
#pragma unroll
                for (int j = 0; j < 8; ++j)
#pragma unroll
                    for (int c = 0; c < 2; ++c) {
                        float v = acc[f][j][2 * h + c];
                        if (v >= thr) {
                            int pos = atomicAdd(&cnt[r], 1);
                            if (pos < CCAP) {
                                candV[r * CCAP + pos] = v;
                                candI[r * CCAP + pos] =
                                    mt * 128 + wx * 64 + j * 8 + 2 * t + c;
                            }
                        }
                    }
            }
        __syncthreads();  // all reads of buf (mt%3) done

        if (mt + 2 < 16) {  // prefetch tile mt+2 into buf (mt+2)%3
            int nb_ = SM_BT0 + ((mt + 2) % 3) * 34816;
#pragma unroll
            for (int i = tid; i < 2048; i += 256) {
                int row = i >> 4, c = i & 15;
                CP_ASYNC16(sb + nb_ + row * LDB + c * 16,
                           esrc + ((size_t)(mt + 2) * 128 + row) * 256 + c * 16);
            }
            CP_COMMIT();
        }
    }

    // publish per-warp-half row maxima
    if (t == 0) {
#pragma unroll
        for (int f = 0; f < 2; ++f)
#pragma unroll
            for (int h = 0; h < 2; ++h)
                hmax[(32 * wy + 16 * f + 8 * h + g) * 2 + wx] = rmax[f][h];
    }
    __syncthreads();

    // filter + exact fp32 rescore: 2 threads per row; then write output
    {
        int r = tid >> 1;
        float Mb = fmaxf(hmax[r * 2], hmax[r * 2 + 1]);
        float thr = Mb - MARGIN;
        int n = min(cnt[r], CCAP);
        float bv = -1e30f;
        int bi = 0x7fffffff;
        const float4* xa = (const float4*)(g_cn + ((size_t)b * NL + l0 + r) * ND);
        for (int e = (tid & 1); e < n; e += 2) {
            if (candV[r * CCAP + e] < thr) continue;
            int m = candI[r * CCAP + e];
            const float4* xb = (const float4*)(g_en + ((size_t)b * NL + m) * ND);
            float s0 = 0, s1 = 0, s2 = 0, s3 = 0;
#pragma unroll
            for (int q = 0; q < 32; ++q) {
                float4 A = xa[q];
                float4 Bv = xb[q];
                s0 += A.x * Bv.x; s1 += A.y * Bv.y;
                s2 += A.z * Bv.z; s3 += A.w * Bv.w;
            }
            float s = (s0 + s1) + (s2 + s3);
            if (s > bv || (s == bv && m < bi)) { bv = s; bi = m; }
        }
        __syncthreads();
        candV[tid] = bv;
        candI[tid] = bi;
        __syncthreads();
        if (tid < 128) {
            float v0 = candV[tid * 2], v1 = candV[tid * 2 + 1];
            int i0 = candI[tid * 2], i1 = candI[tid * 2 + 1];
            int best = (v1 > v0 || (v1 == v0 && i1 < i0)) ? i1 : i0;
            float bb2 = b2[0];
            out[b * NL + l0 + tid] = g_scn[b * NL + l0 + tid] +
                                     g_sen[b * NL + best] + 2.0f * bb2;
        }
    }
}

// =================================================================
// launch
// =================================================================
extern "C" void kernel_launch(void* const* d_in, const int* in_sizes, int n_in,
                              void* d_out, int out_size) {
    const float* context = (const float*)d_in[0];
    const float* W1      = (const float*)d_in[1];
    const float* b1      = (const float*)d_in[2];
    const float* W2      = (const float*)d_in[3];
    const float* b2      = (const float*)d_in[4];
    float* out           = (float*)d_out;

    {
        int warps = 2 * NB * NL;
        int threads = 256;
        int blocks = (warps * 32 + threads - 1) / threads;
        norm_kernel<<<blocks, threads>>>(context);
    }
    {
        cudaFuncSetAttribute(smlp_kernel,
                             cudaFuncAttributeMaxDynamicSharedMemorySize,
                             SMLP_TOTAL);
        smlp_kernel<<<2 * NB * NL / 64, 128, SMLP_TOTAL>>>(W1, b1, W2);
    }
    {
        cudaFuncSetAttribute(simarg_kernel,
                             cudaFuncAttributeMaxDynamicSharedMemorySize,
                             SM_SIM_TOTAL);
        dim3 grid(NL / 128, NB);
        simarg_kernel<<<grid, 256, SM_SIM_TOTAL>>>(b2, out);
    }
}